// round 7
// baseline (speedup 1.0000x reference)
#include <cuda_runtime.h>
#include <stdint.h>
#include <math.h>

#define B_DIM 8192
#define C_DIM 2048
#define F_DIM 2048

#define BM 128
#define BN 128
#define BK 32
#define NKI (F_DIM / BK)     // 64 k-iterations
#define NSTG 3
#define ROWW 32                                   // words per row (XOR swizzle)
#define STAGE_FLOATS (2 * 128 * ROWW)             // A tile + B tile per stage (32KB)
#define SMEM_GEMM (NSTG * STAGE_FLOATS * 4)       // 96KB -> 2 CTAs/SM

// ---------------- device scratch (no allocations allowed) -------------------
// K-PERMUTED layout: within each 16-float k-group g, element k is stored at
// slot g*16 + (k%4)*4 + (k/4)%4  => a thread's fragment k-values
// {lq, lq+4, lq+8, lq+12} are one contiguous float4.
__device__ float g_A [(size_t)B_DIM * F_DIM];   // tf32(x/var), k-permuted
__device__ float g_Bm[(size_t)C_DIM * F_DIM];   // tf32(means), k-permuted
__device__ float g_xx[B_DIM];                   // ||x/var||^2 (exact fp32)
__device__ float g_m2[C_DIM];                   // ||means||^2

// ---------------- helpers ----------------------------------------------------
__device__ __forceinline__ uint32_t smem_u32(const void* p) {
    uint32_t a;
    asm("{ .reg .u64 t; cvta.to.shared.u64 t, %1; cvt.u32.u64 %0, t; }" : "=r"(a) : "l"(p));
    return a;
}
__device__ __forceinline__ float tf32_round(float v) {
    uint32_t u;
    asm("cvt.rna.tf32.f32 %0, %1;" : "=r"(u) : "f"(v));
    return __uint_as_float(u);
}
#define CP_ASYNC16(dst, src) \
    asm volatile("cp.async.cg.shared.global [%0], [%1], 16;" :: "r"(dst), "l"(src))
#define CP_COMMIT() asm volatile("cp.async.commit_group;" ::: "memory")
#define CP_WAIT(n)  asm volatile("cp.async.wait_group %0;" :: "n"(n) : "memory")

__device__ __forceinline__ void mma_tf32(float c[4], uint32_t a0, uint32_t a1,
                                         uint32_t a2, uint32_t a3,
                                         uint32_t b0, uint32_t b1) {
    asm volatile(
        "mma.sync.aligned.m16n8k8.row.col.f32.tf32.tf32.f32 "
        "{%0,%1,%2,%3}, {%4,%5,%6,%7}, {%8,%9}, {%0,%1,%2,%3};"
        : "+f"(c[0]), "+f"(c[1]), "+f"(c[2]), "+f"(c[3])
        : "r"(a0), "r"(a1), "r"(a2), "r"(a3), "r"(b0), "r"(b1));
}

// ---------------------------------------------------------------------------
// Convert: scale (x only) + tf32 round + row ||.||^2 + K-PERMUTED store.
// ---------------------------------------------------------------------------
__global__ void __launch_bounds__(256)
convert_kernel(const float* __restrict__ src, const float* __restrict__ varp, int x_mode)
{
    __shared__ float sm[8];
    const int row = blockIdx.x;
    const float inv = x_mode ? (1.0f / varp[0]) : 1.0f;
    float* dst = (x_mode ? g_A : g_Bm) + (size_t)row * F_DIM;
    const float4* p = (const float4*)(src + (size_t)row * F_DIM);

    float s = 0.f;
    for (int j = threadIdx.x; j < F_DIM / 4; j += 256) {
        float4 v = p[j];
        float a0 = v.x * inv, a1 = v.y * inv, a2 = v.z * inv, a3 = v.w * inv;
        s += a0 * a0 + a1 * a1 + a2 * a2 + a3 * a3;
        const int base = (j >> 2) * 16 + (j & 3);
        dst[base +  0] = tf32_round(a0);
        dst[base +  4] = tf32_round(a1);
        dst[base +  8] = tf32_round(a2);
        dst[base + 12] = tf32_round(a3);
    }
    int lane = threadIdx.x & 31, wid = threadIdx.x >> 5;
    #pragma unroll
    for (int o = 16; o > 0; o >>= 1) s += __shfl_down_sync(0xffffffffu, s, o);
    if (lane == 0) sm[wid] = s;
    __syncthreads();
    if (threadIdx.x == 0) {
        float t = sm[0];
        #pragma unroll
        for (int w = 1; w < 8; w++) t += sm[w];
        (x_mode ? g_xx : g_m2)[row] = t;
    }
}

// ---------------------------------------------------------------------------
// TF32 mma.sync GEMM + fused distance epilogue.
// 128x128x32 tile, 8 warps 2x4 (warp tile 64x32), 3-stage cp.async,
// 2 CTAs/SM; inner loop restructured to keep live regs < 128 (no spills).
// ---------------------------------------------------------------------------
__global__ void __launch_bounds__(256, 2)
gemm_kernel(float* __restrict__ expo, float* __restrict__ dist)
{
    extern __shared__ float smem[];

    const int tid  = threadIdx.x;
    const int wid  = tid >> 5;
    const int lane = tid & 31;
    const int lq   = lane & 3;
    const int lr   = lane >> 2;
    const int wm   = (wid >> 2) * 64;   // warp M offset (0,64)
    const int wn   = (wid & 3) * 32;    // warp N offset (0,32,64,96)
    const int blockM = blockIdx.y * BM;
    const int blockN = blockIdx.x * BN;

    const uint32_t sbase = smem_u32(smem);

    float acc[4][4][4];
    #pragma unroll
    for (int i = 0; i < 4; i++)
        #pragma unroll
        for (int j = 0; j < 4; j++)
            #pragma unroll
            for (int e = 0; e < 4; e++) acc[i][j][e] = 0.f;

    const float* gA = g_A  + (size_t)blockM * F_DIM;
    const float* gB = g_Bm + (size_t)blockN * F_DIM;

    auto load_stage = [&](int stage, int kiter) {
        const uint32_t abase = sbase + (uint32_t)(stage * STAGE_FLOATS) * 4u;
        const uint32_t bbase = abase + 128u * ROWW * 4u;
        const int k0 = kiter * BK;
        #pragma unroll
        for (int t = 0; t < 4; t++) {
            int id = tid + (t << 8);
            int m = id >> 3, c = id & 7;
            uint32_t w = (uint32_t)((c * 4) ^ ((m & 1) << 4));
            CP_ASYNC16(abase + (uint32_t)(m * ROWW + w) * 4u,
                       gA + (size_t)m * F_DIM + k0 + c * 4);
        }
        #pragma unroll
        for (int t = 0; t < 4; t++) {
            int id = tid + (t << 8);
            int m = id >> 3, c = id & 7;
            uint32_t w = (uint32_t)((c * 4) ^ ((m & 1) << 4));
            CP_ASYNC16(bbase + (uint32_t)(m * ROWW + w) * 4u,
                       gB + (size_t)m * F_DIM + k0 + c * 4);
        }
    };

    load_stage(0, 0); CP_COMMIT();
    load_stage(1, 1); CP_COMMIT();

    // epilogue scalars prefetched early (tiny, L2-resident after first tiles)
    float xxv[8];
    #pragma unroll
    for (int mt = 0; mt < 4; mt++) {
        xxv[2 * mt]     = g_xx[blockM + wm + mt * 16 + lr];
        xxv[2 * mt + 1] = g_xx[blockM + wm + mt * 16 + lr + 8];
    }

    int stage = 0, nstage = 2;  // stage being consumed / next stage slot to fill
    for (int i = 0; i < NKI; i++) {
        CP_WAIT(NSTG - 2);
        __syncthreads();

        const float* A  = smem + stage * STAGE_FLOATS;
        const float* Bf = A + 128 * ROWW;

        #pragma unroll
        for (int g = 0; g < 2; g++) {               // 16-float k-group
            const int wbase = g * 16 + lq * 4;
            float4 b4[4];
            #pragma unroll
            for (int nt = 0; nt < 4; nt++) {
                const int n0 = wn + nt * 8 + lr;
                b4[nt] = *(const float4*)(Bf + n0 * ROWW + (wbase ^ ((n0 & 1) << 4)));
            }
            // per-mt A load (with one-step prefetch) + immediate 8 MMAs
            const int r0_0 = wm + lr;
            float4 al = *(const float4*)(A + r0_0 * ROWW + (wbase ^ ((r0_0 & 1) << 4)));
            float4 ah = *(const float4*)(A + (r0_0 + 8) * ROWW + (wbase ^ (((r0_0 + 8) & 1) << 4)));
            #pragma unroll
            for (int mt = 0; mt < 4; mt++) {
                float4 cl = al, ch = ah;
                if (mt < 3) {
                    const int rn = wm + (mt + 1) * 16 + lr;
                    al = *(const float4*)(A + rn * ROWW + (wbase ^ ((rn & 1) << 4)));
                    ah = *(const float4*)(A + (rn + 8) * ROWW + (wbase ^ (((rn + 8) & 1) << 4)));
                }
                #pragma unroll
                for (int nt = 0; nt < 4; nt++)
                    mma_tf32(acc[mt][nt],
                             __float_as_uint(cl.x), __float_as_uint(ch.x),
                             __float_as_uint(cl.y), __float_as_uint(ch.y),
                             __float_as_uint(b4[nt].x), __float_as_uint(b4[nt].y));
                #pragma unroll
                for (int nt = 0; nt < 4; nt++)
                    mma_tf32(acc[mt][nt],
                             __float_as_uint(cl.z), __float_as_uint(ch.z),
                             __float_as_uint(cl.w), __float_as_uint(ch.w),
                             __float_as_uint(b4[nt].z), __float_as_uint(b4[nt].w));
            }
        }

        const int nxt = i + NSTG - 1;
        if (nxt < NKI) load_stage(nstage, nxt);
        CP_COMMIT();
        stage  = (stage  == NSTG - 1) ? 0 : stage + 1;
        nstage = (nstage == NSTG - 1) ? 0 : nstage + 1;
    }

    // -------- epilogue: d = sqrt(max(xx + m2 - 2*cross, 0)) --------
    #pragma unroll
    for (int mt = 0; mt < 4; mt++) {
        const int r0 = blockM + wm + mt * 16 + lr;
        const int r1 = r0 + 8;
        const float xx0 = xxv[2 * mt];
        const float xx1 = xxv[2 * mt + 1];
        #pragma unroll
        for (int nt = 0; nt < 4; nt++) {
            const int c0 = blockN + wn + nt * 8 + 2 * lq;
            const float2 m2 = *(const float2*)(g_m2 + c0);
            float d00 = sqrtf(fmaxf(fmaf(-2.f, acc[mt][nt][0], xx0 + m2.x), 0.f));
            float d01 = sqrtf(fmaxf(fmaf(-2.f, acc[mt][nt][1], xx0 + m2.y), 0.f));
            float d10 = sqrtf(fmaxf(fmaf(-2.f, acc[mt][nt][2], xx1 + m2.x), 0.f));
            float d11 = sqrtf(fmaxf(fmaf(-2.f, acc[mt][nt][3], xx1 + m2.y), 0.f));
            *(float2*)(dist + (size_t)r0 * C_DIM + c0) = make_float2(d00, d01);
            *(float2*)(dist + (size_t)r1 * C_DIM + c0) = make_float2(d10, d11);
            *(float2*)(expo + (size_t)r0 * C_DIM + c0) = make_float2(-d00, -d01);
            *(float2*)(expo + (size_t)r1 * C_DIM + c0) = make_float2(-d10, -d11);
        }
    }
}

// ---------------------------------------------------------------------------
// Row softmax over C=2048: one block per row.
// ---------------------------------------------------------------------------
__global__ void __launch_bounds__(256)
softmax_kernel(const float* __restrict__ expo, float* __restrict__ probs)
{
    __shared__ float sm[32];
    const int row = blockIdx.x;
    const int t = threadIdx.x;
    const float4* e = (const float4*)(expo + (size_t)row * C_DIM);
    float4* p = (float4*)(probs + (size_t)row * C_DIM);

    float4 v0 = e[t];
    float4 v1 = e[t + 256];

    float mx = fmaxf(fmaxf(fmaxf(v0.x, v0.y), fmaxf(v0.z, v0.w)),
                     fmaxf(fmaxf(v1.x, v1.y), fmaxf(v1.z, v1.w)));
    int lane = t & 31, wid = t >> 5;
    #pragma unroll
    for (int o = 16; o > 0; o >>= 1) mx = fmaxf(mx, __shfl_down_sync(0xffffffffu, mx, o));
    if (lane == 0) sm[wid] = mx;
    __syncthreads();
    if (t == 0) {
        float m = sm[0];
        #pragma unroll
        for (int w = 1; w < 8; w++) m = fmaxf(m, sm[w]);
        sm[0] = m;
    }
    __syncthreads();
    mx = sm[0];
    __syncthreads();

    float4 x0, x1;
    x0.x = expf(v0.x - mx); x0.y = expf(v0.y - mx);
    x0.z = expf(v0.z - mx); x0.w = expf(v0.w - mx);
    x1.x = expf(v1.x - mx); x1.y = expf(v1.y - mx);
    x1.z = expf(v1.z - mx); x1.w = expf(v1.w - mx);
    float s = x0.x + x0.y + x0.z + x0.w + x1.x + x1.y + x1.z + x1.w;
    #pragma unroll
    for (int o = 16; o > 0; o >>= 1) s += __shfl_down_sync(0xffffffffu, s, o);
    if (lane == 0) sm[wid] = s;
    __syncthreads();
    if (t == 0) {
        float acc = sm[0];
        #pragma unroll
        for (int w = 1; w < 8; w++) acc += sm[w];
        sm[0] = acc;
    }
    __syncthreads();
    const float rinv = 1.0f / sm[0];

    x0.x *= rinv; x0.y *= rinv; x0.z *= rinv; x0.w *= rinv;
    x1.x *= rinv; x1.y *= rinv; x1.z *= rinv; x1.w *= rinv;
    p[t] = x0;
    p[t + 256] = x1;
}

// ---------------------------------------------------------------------------
extern "C" void kernel_launch(void* const* d_in, const int* in_sizes, int n_in,
                              void* d_out, int out_size)
{
    const float* x     = (const float*)d_in[0];
    const float* means = (const float*)d_in[1];
    const float* var   = (const float*)d_in[2];

    float* probs = (float*)d_out;
    float* expo  = probs + (size_t)B_DIM * C_DIM;
    float* dist  = expo  + (size_t)B_DIM * C_DIM;

    cudaFuncSetAttribute(gemm_kernel, cudaFuncAttributeMaxDynamicSharedMemorySize, SMEM_GEMM);

    convert_kernel<<<B_DIM, 256>>>(x, var, 1);
    convert_kernel<<<C_DIM, 256>>>(means, var, 0);
    gemm_kernel<<<dim3(C_DIM / BN, B_DIM / BM), 256, SMEM_GEMM>>>(expo, dist);
    softmax_kernel<<<B_DIM, 256>>>(expo, probs);
}

// round 8
// speedup vs baseline: 1.0396x; 1.0396x over previous
#include <cuda_runtime.h>
#include <stdint.h>
#include <math.h>

#define B_DIM 8192
#define C_DIM 2048
#define F_DIM 2048

#define BM 128
#define BN 128
#define BK 32
#define NKI (F_DIM / BK)     // 64 k-iterations
#define NSTG 3
#define ROWW 32                                   // words per row (XOR swizzle)
#define STAGE_FLOATS (2 * 128 * ROWW)             // A tile + B tile per stage (32KB)
#define SMEM_GEMM (NSTG * STAGE_FLOATS * 4)       // 96KB -> 2 CTAs/SM

// ---------------- device scratch (no allocations allowed) -------------------
// K-PERMUTED layout: within each 16-float k-group g, element k is stored at
// slot g*16 + (k%4)*4 + (k/4)%4  => a thread's fragment k-values
// {lq, lq+4, lq+8, lq+12} are one contiguous float4.
__device__ float g_A [(size_t)B_DIM * F_DIM];   // tf32(x/var), k-permuted
__device__ float g_Bm[(size_t)C_DIM * F_DIM];   // tf32(means), k-permuted
__device__ float g_xx[B_DIM];                   // ||x/var||^2 (exact fp32)
__device__ float g_m2[C_DIM];                   // ||means||^2

// ---------------- helpers ----------------------------------------------------
__device__ __forceinline__ uint32_t smem_u32(const void* p) {
    uint32_t a;
    asm("{ .reg .u64 t; cvta.to.shared.u64 t, %1; cvt.u32.u64 %0, t; }" : "=r"(a) : "l"(p));
    return a;
}
__device__ __forceinline__ float tf32_round(float v) {
    uint32_t u;
    asm("cvt.rna.tf32.f32 %0, %1;" : "=r"(u) : "f"(v));
    return __uint_as_float(u);
}
#define CP_ASYNC16(dst, src) \
    asm volatile("cp.async.cg.shared.global [%0], [%1], 16;" :: "r"(dst), "l"(src))
#define CP_COMMIT() asm volatile("cp.async.commit_group;" ::: "memory")
#define CP_WAIT(n)  asm volatile("cp.async.wait_group %0;" :: "n"(n) : "memory")

__device__ __forceinline__ void mma_tf32(float c[4], uint32_t a0, uint32_t a1,
                                         uint32_t a2, uint32_t a3,
                                         uint32_t b0, uint32_t b1) {
    asm volatile(
        "mma.sync.aligned.m16n8k8.row.col.f32.tf32.tf32.f32 "
        "{%0,%1,%2,%3}, {%4,%5,%6,%7}, {%8,%9}, {%0,%1,%2,%3};"
        : "+f"(c[0]), "+f"(c[1]), "+f"(c[2]), "+f"(c[3])
        : "r"(a0), "r"(a1), "r"(a2), "r"(a3), "r"(b0), "r"(b1));
}

// ---------------------------------------------------------------------------
// Convert: scale (x only) + tf32 round + row ||.||^2 + K-PERMUTED store.
// Permute via smem so BOTH gmem loads and gmem stores are coalesced float4.
// One fused launch: row < B_DIM -> x, else means.
// ---------------------------------------------------------------------------
__global__ void __launch_bounds__(256)
convert_kernel(const float* __restrict__ x, const float* __restrict__ means,
               const float* __restrict__ varp)
{
    __shared__ float sperm[F_DIM];   // 8KB: permuted row
    __shared__ float sm[8];

    const int rid = blockIdx.x;
    const int x_mode = rid < B_DIM;
    const int row = x_mode ? rid : rid - B_DIM;
    const float inv = x_mode ? (1.0f / varp[0]) : 1.0f;
    const float* src = x_mode ? x : means;
    float* dst = (x_mode ? g_A : g_Bm) + (size_t)row * F_DIM;

    const float4* p = (const float4*)(src + (size_t)row * F_DIM);
    float s = 0.f;
    #pragma unroll
    for (int j = threadIdx.x; j < F_DIM / 4; j += 256) {
        float4 v = p[j];
        float a0 = v.x * inv, a1 = v.y * inv, a2 = v.z * inv, a3 = v.w * inv;
        s += a0 * a0 + a1 * a1 + a2 * a2 + a3 * a3;
        // k = 4j+e ; group g = j>>2 ; slot = g*16 + e*4 + (j&3)
        const int base = (j >> 2) * 16 + (j & 3);
        sperm[base +  0] = tf32_round(a0);
        sperm[base +  4] = tf32_round(a1);
        sperm[base +  8] = tf32_round(a2);
        sperm[base + 12] = tf32_round(a3);
    }
    __syncthreads();
    // coalesced float4 stores of the permuted row
    #pragma unroll
    for (int j = threadIdx.x; j < F_DIM / 4; j += 256)
        *(float4*)(dst + j * 4) = *(const float4*)(sperm + j * 4);

    int lane = threadIdx.x & 31, wid = threadIdx.x >> 5;
    #pragma unroll
    for (int o = 16; o > 0; o >>= 1) s += __shfl_down_sync(0xffffffffu, s, o);
    if (lane == 0) sm[wid] = s;
    __syncthreads();
    if (threadIdx.x == 0) {
        float t = sm[0];
        #pragma unroll
        for (int w = 1; w < 8; w++) t += sm[w];
        (x_mode ? g_xx : g_m2)[row] = t;
    }
}

// ---------------------------------------------------------------------------
// TF32 mma.sync GEMM + fused distance epilogue.  (R6-proven mainloop shape,
// with next-stage cp.async issued BEFORE the MMA block.)
// 128x128x32 tile, 8 warps 2x4 (warp tile 64x32), 3-stage cp.async, 2 CTAs/SM.
// ---------------------------------------------------------------------------
__global__ void __launch_bounds__(256, 2)
gemm_kernel(float* __restrict__ expo, float* __restrict__ dist)
{
    extern __shared__ float smem[];

    const int tid  = threadIdx.x;
    const int wid  = tid >> 5;
    const int lane = tid & 31;
    const int lq   = lane & 3;
    const int lr   = lane >> 2;
    const int wm   = (wid >> 2) * 64;   // warp M offset (0,64)
    const int wn   = (wid & 3) * 32;    // warp N offset (0,32,64,96)
    const int blockM = blockIdx.y * BM;
    const int blockN = blockIdx.x * BN;

    const uint32_t sbase = smem_u32(smem);

    float acc[4][4][4];
    #pragma unroll
    for (int i = 0; i < 4; i++)
        #pragma unroll
        for (int j = 0; j < 4; j++)
            #pragma unroll
            for (int e = 0; e < 4; e++) acc[i][j][e] = 0.f;

    const float* gA = g_A  + (size_t)blockM * F_DIM;
    const float* gB = g_Bm + (size_t)blockN * F_DIM;

    auto load_stage = [&](int stage, int kiter) {
        const uint32_t abase = sbase + (uint32_t)(stage * STAGE_FLOATS) * 4u;
        const uint32_t bbase = abase + 128u * ROWW * 4u;
        const int k0 = kiter * BK;
        #pragma unroll
        for (int t = 0; t < 4; t++) {
            int id = tid + (t << 8);
            int m = id >> 3, c = id & 7;
            uint32_t w = (uint32_t)((c * 4) ^ ((m & 1) << 4));
            CP_ASYNC16(abase + (uint32_t)(m * ROWW + w) * 4u,
                       gA + (size_t)m * F_DIM + k0 + c * 4);
        }
        #pragma unroll
        for (int t = 0; t < 4; t++) {
            int id = tid + (t << 8);
            int m = id >> 3, c = id & 7;
            uint32_t w = (uint32_t)((c * 4) ^ ((m & 1) << 4));
            CP_ASYNC16(bbase + (uint32_t)(m * ROWW + w) * 4u,
                       gB + (size_t)m * F_DIM + k0 + c * 4);
        }
    };

    load_stage(0, 0); CP_COMMIT();
    load_stage(1, 1); CP_COMMIT();

    int stage = 0, nstage = 2;
    for (int i = 0; i < NKI; i++) {
        CP_WAIT(NSTG - 2);
        __syncthreads();

        // issue next-stage loads FIRST so LSU overlaps the MMA block
        const int nxt = i + NSTG - 1;
        if (nxt < NKI) load_stage(nstage, nxt);
        CP_COMMIT();

        const float* A  = smem + stage * STAGE_FLOATS;
        const float* Bf = A + 128 * ROWW;

        #pragma unroll
        for (int g = 0; g < 2; g++) {               // 16-float k-group
            const int wbase = g * 16 + lq * 4;
            float4 a4l[4], a4h[4], b4[4];
            #pragma unroll
            for (int mt = 0; mt < 4; mt++) {
                const int r0 = wm + mt * 16 + lr;
                const int r1 = r0 + 8;
                a4l[mt] = *(const float4*)(A + r0 * ROWW + (wbase ^ ((r0 & 1) << 4)));
                a4h[mt] = *(const float4*)(A + r1 * ROWW + (wbase ^ ((r1 & 1) << 4)));
            }
            #pragma unroll
            for (int nt = 0; nt < 4; nt++) {
                const int n0 = wn + nt * 8 + lr;
                b4[nt] = *(const float4*)(Bf + n0 * ROWW + (wbase ^ ((n0 & 1) << 4)));
            }
            #pragma unroll
            for (int mt = 0; mt < 4; mt++)
                #pragma unroll
                for (int nt = 0; nt < 4; nt++)
                    mma_tf32(acc[mt][nt],
                             __float_as_uint(a4l[mt].x), __float_as_uint(a4h[mt].x),
                             __float_as_uint(a4l[mt].y), __float_as_uint(a4h[mt].y),
                             __float_as_uint(b4[nt].x),  __float_as_uint(b4[nt].y));
            #pragma unroll
            for (int mt = 0; mt < 4; mt++)
                #pragma unroll
                for (int nt = 0; nt < 4; nt++)
                    mma_tf32(acc[mt][nt],
                             __float_as_uint(a4l[mt].z), __float_as_uint(a4h[mt].z),
                             __float_as_uint(a4l[mt].w), __float_as_uint(a4h[mt].w),
                             __float_as_uint(b4[nt].z),  __float_as_uint(b4[nt].w));
        }

        stage  = (stage  == NSTG - 1) ? 0 : stage + 1;
        nstage = (nstage == NSTG - 1) ? 0 : nstage + 1;
    }

    // -------- epilogue: d = sqrt(max(xx + m2 - 2*cross, 0)) --------
    #pragma unroll
    for (int mt = 0; mt < 4; mt++) {
        const int r0 = blockM + wm + mt * 16 + lr;
        const int r1 = r0 + 8;
        const float xx0 = g_xx[r0];
        const float xx1 = g_xx[r1];
        #pragma unroll
        for (int nt = 0; nt < 4; nt++) {
            const int c0 = blockN + wn + nt * 8 + 2 * lq;
            const float2 m2 = *(const float2*)(g_m2 + c0);
            float d00 = sqrtf(fmaxf(fmaf(-2.f, acc[mt][nt][0], xx0 + m2.x), 0.f));
            float d01 = sqrtf(fmaxf(fmaf(-2.f, acc[mt][nt][1], xx0 + m2.y), 0.f));
            float d10 = sqrtf(fmaxf(fmaf(-2.f, acc[mt][nt][2], xx1 + m2.x), 0.f));
            float d11 = sqrtf(fmaxf(fmaf(-2.f, acc[mt][nt][3], xx1 + m2.y), 0.f));
            *(float2*)(dist + (size_t)r0 * C_DIM + c0) = make_float2(d00, d01);
            *(float2*)(dist + (size_t)r1 * C_DIM + c0) = make_float2(d10, d11);
            *(float2*)(expo + (size_t)r0 * C_DIM + c0) = make_float2(-d00, -d01);
            *(float2*)(expo + (size_t)r1 * C_DIM + c0) = make_float2(-d10, -d11);
        }
    }
}

// ---------------------------------------------------------------------------
// Row softmax over C=2048: one block per row.
// ---------------------------------------------------------------------------
__global__ void __launch_bounds__(256)
softmax_kernel(const float* __restrict__ expo, float* __restrict__ probs)
{
    __shared__ float sm[32];
    const int row = blockIdx.x;
    const int t = threadIdx.x;
    const float4* e = (const float4*)(expo + (size_t)row * C_DIM);
    float4* p = (float4*)(probs + (size_t)row * C_DIM);

    float4 v0 = e[t];
    float4 v1 = e[t + 256];

    float mx = fmaxf(fmaxf(fmaxf(v0.x, v0.y), fmaxf(v0.z, v0.w)),
                     fmaxf(fmaxf(v1.x, v1.y), fmaxf(v1.z, v1.w)));
    int lane = t & 31, wid = t >> 5;
    #pragma unroll
    for (int o = 16; o > 0; o >>= 1) mx = fmaxf(mx, __shfl_down_sync(0xffffffffu, mx, o));
    if (lane == 0) sm[wid] = mx;
    __syncthreads();
    if (t == 0) {
        float m = sm[0];
        #pragma unroll
        for (int w = 1; w < 8; w++) m = fmaxf(m, sm[w]);
        sm[0] = m;
    }
    __syncthreads();
    mx = sm[0];
    __syncthreads();

    float4 x0, x1;
    x0.x = expf(v0.x - mx); x0.y = expf(v0.y - mx);
    x0.z = expf(v0.z - mx); x0.w = expf(v0.w - mx);
    x1.x = expf(v1.x - mx); x1.y = expf(v1.y - mx);
    x1.z = expf(v1.z - mx); x1.w = expf(v1.w - mx);
    float s = x0.x + x0.y + x0.z + x0.w + x1.x + x1.y + x1.z + x1.w;
    #pragma unroll
    for (int o = 16; o > 0; o >>= 1) s += __shfl_down_sync(0xffffffffu, s, o);
    if (lane == 0) sm[wid] = s;
    __syncthreads();
    if (t == 0) {
        float acc = sm[0];
        #pragma unroll
        for (int w = 1; w < 8; w++) acc += sm[w];
        sm[0] = acc;
    }
    __syncthreads();
    const float rinv = 1.0f / sm[0];

    x0.x *= rinv; x0.y *= rinv; x0.z *= rinv; x0.w *= rinv;
    x1.x *= rinv; x1.y *= rinv; x1.z *= rinv; x1.w *= rinv;
    p[t] = x0;
    p[t + 256] = x1;
}

// ---------------------------------------------------------------------------
extern "C" void kernel_launch(void* const* d_in, const int* in_sizes, int n_in,
                              void* d_out, int out_size)
{
    const float* x     = (const float*)d_in[0];
    const float* means = (const float*)d_in[1];
    const float* var   = (const float*)d_in[2];

    float* probs = (float*)d_out;
    float* expo  = probs + (size_t)B_DIM * C_DIM;
    float* dist  = expo  + (size_t)B_DIM * C_DIM;

    cudaFuncSetAttribute(gemm_kernel, cudaFuncAttributeMaxDynamicSharedMemorySize, SMEM_GEMM);

    convert_kernel<<<B_DIM + C_DIM, 256>>>(x, means, var);
    gemm_kernel<<<dim3(C_DIM / BN, B_DIM / BM), 256, SMEM_GEMM>>>(expo, dist);
    softmax_kernel<<<B_DIM, 256>>>(expo, probs);
}